// round 15
// baseline (speedup 1.0000x reference)
#include <cuda_runtime.h>
#include <cuda_bf16.h>
#include <cstdint>

#define BDIM 512
#define FDIM 1024
#define H1D  512
#define H2D  256
#define OUTD 128
#define KDD  5
#define NMD  (OUTD*KDD)   // 640
#define ZD   384
#define LOG2E 1.44269504f

// Prepped weights: bf16 hi/lo, transposed to [n][k]
#define WOFF_W1 0
#define WOFF_W2 524288
#define WOFF_T  655360
#define WOFF_W3 819200
#define WTOT    868352
__device__ __nv_bfloat16 g_Wbh[WTOT];
__device__ __nv_bfloat16 g_Wbl[WTOT];

// bf16 hi/lo activations
__device__ __nv_bfloat16 g_xbh[BDIM * FDIM], g_xbl[BDIM * FDIM];
__device__ __nv_bfloat16 g_h1bh[BDIM * H1D], g_h1bl[BDIM * H1D];
__device__ __nv_bfloat16 g_zbh[BDIM * ZD],  g_zbl[BDIM * ZD];   // h2 | o_b

// fp32 split-K partials
__device__ float g_p1[4 * BDIM * H1D];
__device__ float g_p2[4 * BDIM * H2D];
__device__ float g_p3[2 * BDIM * NMD];
__device__ float g_p4[3 * BDIM * OUTD];

__device__ __forceinline__ float lrelu(float v) { return fmaxf(v, 0.2f * v); }

__device__ __forceinline__ uint32_t smem_u32(const void* p) {
    uint32_t a;
    asm("{ .reg .u64 t; cvta.to.shared.u64 t, %1; cvt.u32.u64 %0, t; }"
        : "=r"(a) : "l"(p));
    return a;
}
__device__ __forceinline__ void ldmx4(uint32_t* r, uint32_t addr) {
    asm volatile("ldmatrix.sync.aligned.m8n8.x4.shared.b16 {%0,%1,%2,%3}, [%4];"
                 : "=r"(r[0]), "=r"(r[1]), "=r"(r[2]), "=r"(r[3]) : "r"(addr));
}
__device__ __forceinline__ void mma16816(float* d, const uint32_t* a,
                                         uint32_t b0, uint32_t b1) {
    asm volatile("mma.sync.aligned.m16n8k16.row.col.f32.bf16.bf16.f32 "
                 "{%0,%1,%2,%3}, {%4,%5,%6,%7}, {%8,%9}, {%0,%1,%2,%3};"
                 : "+f"(d[0]), "+f"(d[1]), "+f"(d[2]), "+f"(d[3])
                 : "r"(a[0]), "r"(a[1]), "r"(a[2]), "r"(a[3]), "r"(b0), "r"(b1));
}
__device__ __forceinline__ uint32_t bf16pack(float lo_elem, float hi_elem) {
    uint32_t r;
    asm("cvt.rn.bf16x2.f32 %0, %1, %2;" : "=r"(r) : "f"(hi_elem), "f"(lo_elem));
    return r;
}
__device__ __forceinline__ void cpasync16(uint32_t dst, const void* src) {
    asm volatile("cp.async.cg.shared.global [%0], [%1], 16;"
                 :: "r"(dst), "l"(src) : "memory");
}
#define CP_COMMIT() asm volatile("cp.async.commit_group;" ::: "memory")
#define CP_WAIT1()  asm volatile("cp.async.wait_group 1;" ::: "memory")

// ---------------------------------------------------------------------------
// Prep: weights W [K][N] -> [n][k] bf16 hi/lo (blocks 0..847)
//       x [m][k] fp32 -> bf16 hi/lo straight convert (blocks 848..1359)
// ---------------------------------------------------------------------------
__global__ __launch_bounds__(256)
void prep_k(const float* __restrict__ W1, const float* __restrict__ W2,
            const float* __restrict__ T,  const float* __restrict__ W3,
            const float* __restrict__ x)
{
    int b = blockIdx.x;
    if (b >= 848) {
        int base = (b - 848) * 1024 + threadIdx.x * 4;
        float4 v = *(const float4*)(x + base);
        __nv_bfloat16 hx = __float2bfloat16_rn(v.x);
        __nv_bfloat16 hy = __float2bfloat16_rn(v.y);
        __nv_bfloat16 hz = __float2bfloat16_rn(v.z);
        __nv_bfloat16 hw = __float2bfloat16_rn(v.w);
        uint2 hp = make_uint2(bf16pack(v.x, v.y), bf16pack(v.z, v.w));
        uint2 lp = make_uint2(
            bf16pack(v.x - __bfloat162float(hx), v.y - __bfloat162float(hy)),
            bf16pack(v.z - __bfloat162float(hz), v.w - __bfloat162float(hw)));
        *(uint2*)(g_xbh + base) = hp;
        *(uint2*)(g_xbl + base) = lp;
        return;
    }
    __shared__ float s[32][33];
    const float* src; int K, N; size_t off; int rel;
    if      (b < 512) { src = W1; K = 1024; N = 512; off = WOFF_W1; rel = b; }
    else if (b < 640) { src = W2; K = 512;  N = 256; off = WOFF_W2; rel = b - 512; }
    else if (b < 800) { src = T;  K = 256;  N = 640; off = WOFF_T;  rel = b - 640; }
    else              { src = W3; K = 384;  N = 128; off = WOFF_W3; rel = b - 800; }
    int ktiles = K / 32;
    int k0 = (rel % ktiles) * 32, n0 = (rel / ktiles) * 32;
    int tx = threadIdx.x & 31, ty = threadIdx.x >> 5;

    #pragma unroll
    for (int i = 0; i < 4; i++)
        s[ty + i * 8][tx] = src[(size_t)(k0 + ty + i * 8) * N + n0 + tx];
    __syncthreads();
    #pragma unroll
    for (int i = 0; i < 4; i++) {
        int n = n0 + ty + i * 8, k = k0 + tx;
        float v = s[tx][ty + i * 8];
        __nv_bfloat16 h = __float2bfloat16_rn(v);
        float l = v - __bfloat162float(h);
        g_Wbh[off + (size_t)n * K + k] = h;
        g_Wbl[off + (size_t)n * K + k] = __float2bfloat16_rn(l);
    }
}

// ---------------------------------------------------------------------------
// Pure-bf16 tensor GEMM, cp.async 2-stage pipeline (round-14 proven).
// CTA 64x64, 128 threads, K-chunks of 32, raw fp32 partial per split.
// ---------------------------------------------------------------------------
#define SA_ST 80
#define STG_A_H 0
#define STG_A_L 5120
#define STG_B_H 10240
#define STG_B_L 15360
#define STG_SZ  20480

__global__ __launch_bounds__(128)
void tgemm(const __nv_bfloat16* __restrict__ Abh,
           const __nv_bfloat16* __restrict__ Abl, int lda,
           const __nv_bfloat16* __restrict__ Bhg,
           const __nv_bfloat16* __restrict__ Blg, int Kb,
           float* __restrict__ Cpart, size_t cpStride, int ldc, int Kc)
{
    __shared__ __align__(16) char sb[2 * STG_SZ];
    const int tid = threadIdx.x, lane = tid & 31, wid = tid >> 5;
    const int wm = wid >> 1, wn = wid & 1;
    const int n0 = blockIdx.x * 64, row0 = blockIdx.y * 64;
    const int kbase = blockIdx.z * Kc;
    const uint32_t sbase = smem_u32(sb);

    float acc[2][4][4] = {};

    const int q0 = tid * 2;
    const int r0q = q0 >> 2, qi0 = q0 & 3;
    const int r1q = (q0 + 1) >> 2, qi1 = (q0 + 1) & 3;

    auto issue = [&](int k0, int stg) {
        uint32_t base = sbase + stg * STG_SZ;
        cpasync16(base + STG_A_H + r0q * SA_ST + qi0 * 16,
                  Abh + (size_t)(row0 + r0q) * lda + k0 + qi0 * 8);
        cpasync16(base + STG_A_H + r1q * SA_ST + qi1 * 16,
                  Abh + (size_t)(row0 + r1q) * lda + k0 + qi1 * 8);
        cpasync16(base + STG_A_L + r0q * SA_ST + qi0 * 16,
                  Abl + (size_t)(row0 + r0q) * lda + k0 + qi0 * 8);
        cpasync16(base + STG_A_L + r1q * SA_ST + qi1 * 16,
                  Abl + (size_t)(row0 + r1q) * lda + k0 + qi1 * 8);
        cpasync16(base + STG_B_H + r0q * SA_ST + qi0 * 16,
                  Bhg + (size_t)(n0 + r0q) * Kb + k0 + qi0 * 8);
        cpasync16(base + STG_B_H + r1q * SA_ST + qi1 * 16,
                  Bhg + (size_t)(n0 + r1q) * Kb + k0 + qi1 * 8);
        cpasync16(base + STG_B_L + r0q * SA_ST + qi0 * 16,
                  Blg + (size_t)(n0 + r0q) * Kb + k0 + qi0 * 8);
        cpasync16(base + STG_B_L + r1q * SA_ST + qi1 * 16,
                  Blg + (size_t)(n0 + r1q) * Kb + k0 + qi1 * 8);
    };

    const int nch = Kc / 32;
    issue(kbase, 0);          CP_COMMIT();
    issue(kbase + 32, 1);     CP_COMMIT();

    for (int ch = 0; ch < nch; ch++) {
        CP_WAIT1();
        __syncthreads();

        const uint32_t stg = sbase + (ch & 1) * STG_SZ;
        #pragma unroll
        for (int kt = 0; kt < 2; kt++) {
            uint32_t afh[2][4], afl[2][4], bfh[2][4], bfl[2][4];
            #pragma unroll
            for (int mt = 0; mt < 2; mt++) {
                uint32_t ad = stg + STG_A_H + (wm * 32 + mt * 16 + (lane & 15)) * SA_ST
                            + kt * 32 + ((lane >> 4) << 4);
                ldmx4(afh[mt], ad);
                ldmx4(afl[mt], ad + (STG_A_L - STG_A_H));
            }
            #pragma unroll
            for (int bt = 0; bt < 2; bt++) {
                uint32_t bd = stg + STG_B_H + (wn * 32 + bt * 16 + (lane & 15)) * SA_ST
                            + kt * 32 + ((lane >> 4) << 4);
                ldmx4(bfh[bt], bd);
                ldmx4(bfl[bt], bd + (STG_B_L - STG_B_H));
            }
            #pragma unroll
            for (int mt = 0; mt < 2; mt++)
                #pragma unroll
                for (int j = 0; j < 4; j++) {
                    int t = j >> 1, o = j & 1;
                    uint32_t b0h = bfh[t][o], b1h = bfh[t][o + 2];
                    uint32_t b0l = bfl[t][o], b1l = bfl[t][o + 2];
                    mma16816(acc[mt][j], afh[mt], b0h, b1h);
                    mma16816(acc[mt][j], afl[mt], b0h, b1h);
                    mma16816(acc[mt][j], afh[mt], b0l, b1l);
                }
        }
        __syncthreads();
        if (ch + 2 < nch) issue(kbase + (ch + 2) * 32, ch & 1);
        CP_COMMIT();
    }

    float* cp = Cpart + (size_t)blockIdx.z * cpStride;
    #pragma unroll
    for (int mt = 0; mt < 2; mt++)
        #pragma unroll
        for (int j = 0; j < 4; j++) {
            int r = row0 + wm * 32 + mt * 16 + (lane >> 2);
            int c = n0 + wn * 32 + j * 8 + (lane & 3) * 2;
            *(float2*)&cp[(size_t)r * ldc + c] =
                make_float2(acc[mt][j][0], acc[mt][j][1]);
            *(float2*)&cp[(size_t)(r + 8) * ldc + c] =
                make_float2(acc[mt][j][2], acc[mt][j][3]);
        }
}

// ---------------------------------------------------------------------------
// Reduce SPLIT partials -> lrelu(v+bias) -> bf16 hi/lo (for GEMM1/GEMM2 out).
// ---------------------------------------------------------------------------
template<int SPLIT>
__global__ __launch_bounds__(256)
void reduce_k(const float* __restrict__ P, size_t pstride, int ncols,
              const float* __restrict__ bias,
              __nv_bfloat16* __restrict__ OutH, __nv_bfloat16* __restrict__ OutL,
              int ld_out, int total4)
{
    int f = blockIdx.x * 256 + threadIdx.x;
    if (f >= total4) return;
    int e = f * 4;
    int row = e / ncols, c = e - row * ncols;
    const float* p = P + (size_t)row * ncols + c;
    float4 v = *(const float4*)p;
    #pragma unroll
    for (int s = 1; s < SPLIT; s++) {
        float4 u = *(const float4*)(p + (size_t)s * pstride);
        v.x += u.x; v.y += u.y; v.z += u.z; v.w += u.w;
    }
    float4 bv = *(const float4*)(bias + c);
    v.x = lrelu(v.x + bv.x);
    v.y = lrelu(v.y + bv.y);
    v.z = lrelu(v.z + bv.z);
    v.w = lrelu(v.w + bv.w);
    __nv_bfloat16 hx = __float2bfloat16_rn(v.x);
    __nv_bfloat16 hy = __float2bfloat16_rn(v.y);
    __nv_bfloat16 hz = __float2bfloat16_rn(v.z);
    __nv_bfloat16 hw = __float2bfloat16_rn(v.w);
    uint2 hp = make_uint2(bf16pack(v.x, v.y), bf16pack(v.z, v.w));
    uint2 lp = make_uint2(
        bf16pack(v.x - __bfloat162float(hx), v.y - __bfloat162float(hy)),
        bf16pack(v.z - __bfloat162float(hz), v.w - __bfloat162float(hw)));
    *(uint2*)(OutH + (size_t)row * ld_out + c) = hp;
    *(uint2*)(OutL + (size_t)row * ld_out + c) = lp;
}

// ---------------------------------------------------------------------------
// Pairwise with FUSED GEMM3 split-K reduction:
// loads both p3 partials, sums, scales by log2e into smem, then
// o_b[j,o] = sum_i exp2(-|M[i,o,:]-M[j,o,:]|_1) - 1, f32x2 inner loop.
// grid (o=128, jh=2), 256 threads. Writes bf16 hi/lo into z cols 256+o.
// ---------------------------------------------------------------------------
__global__ __launch_bounds__(256)
void pairwise_k(const float* __restrict__ P3,
                __nv_bfloat16* __restrict__ zbh, __nv_bfloat16* __restrict__ zbl)
{
    __shared__ ulonglong2 sp[BDIM];   // packed (d0,d1),(d2,d3) per i
    __shared__ float      s1[BDIM];   // dim 4
    const int o = blockIdx.x, jh = blockIdx.y;
    const int tid = threadIdx.x;
    const size_t MS = (size_t)BDIM * NMD;

    #pragma unroll
    for (int it = 0; it < 10; it++) {
        int idx = tid + it * 256;
        int i = idx / 5, k = idx - i * 5;
        const float* p = P3 + (size_t)i * NMD + o * KDD + k;
        float v = (p[0] + p[MS]) * LOG2E;
        if (k < 4) ((float*)sp)[i * 4 + k] = v;
        else       s1[i] = v;
    }
    __syncthreads();

    const int j = jh * 256 + tid;
    const float* mj = (const float*)&sp[j];
    float m4e = s1[j];
    unsigned long long nm01, nm23;
    asm("mov.b64 %0, {%1,%2};" : "=l"(nm01) : "f"(-mj[0]), "f"(-mj[1]));
    asm("mov.b64 %0, {%1,%2};" : "=l"(nm23) : "f"(-mj[2]), "f"(-mj[3]));
    const unsigned long long amask = 0x7FFFFFFF7FFFFFFFULL;

    float acc0 = 0.f, acc1 = 0.f;
    #pragma unroll 8
    for (int i = 0; i < BDIM; i++) {
        ulonglong2 v = sp[i];
        float w = s1[i];
        unsigned long long d01, d23, ssum;
        asm("add.rn.f32x2 %0, %1, %2;" : "=l"(d01) : "l"(v.x), "l"(nm01));
        asm("add.rn.f32x2 %0, %1, %2;" : "=l"(d23) : "l"(v.y), "l"(nm23));
        d01 &= amask;
        d23 &= amask;
        asm("add.rn.f32x2 %0, %1, %2;" : "=l"(ssum) : "l"(d01), "l"(d23));
        float lo, hi;
        asm("mov.b64 {%0,%1}, %2;" : "=f"(lo), "=f"(hi) : "l"(ssum));
        float n = (lo + hi) + fabsf(w - m4e);
        float e;
        asm("ex2.approx.f32 %0, %1;" : "=f"(e) : "f"(-n));
        if (i & 1) acc1 += e; else acc0 += e;
    }
    float val = acc0 + acc1 - 1.0f;
    __nv_bfloat16 h = __float2bfloat16_rn(val);
    zbh[(size_t)j * ZD + H2D + o] = h;
    zbl[(size_t)j * ZD + H2D + o] = __float2bfloat16_rn(val - __bfloat162float(h));
}

// ---------------------------------------------------------------------------
// Final with FUSED GEMM4 split-K reduction:
// z3 = lrelu(sum3 p4 + b3); out = z3 @ W4 + b4. One warp per batch row.
// ---------------------------------------------------------------------------
__global__ __launch_bounds__(256)
void final_k(const float* __restrict__ p4, const float* __restrict__ b3,
             const float* __restrict__ W4, const float* __restrict__ b4,
             float* __restrict__ out)
{
    const size_t ZS = (size_t)BDIM * OUTD;
    int gw = blockIdx.x * 8 + (threadIdx.x >> 5);
    int lane = threadIdx.x & 31;
    float sum = 0.f;
    #pragma unroll
    for (int it = 0; it < 4; it++) {
        int k = it * 32 + lane;
        const float* p = p4 + (size_t)gw * OUTD + k;
        float v = (p[0] + p[ZS]) + p[2 * ZS] + b3[k];
        v = lrelu(v);
        sum += v * W4[k];
    }
    #pragma unroll
    for (int off = 16; off; off >>= 1)
        sum += __shfl_xor_sync(0xffffffffu, sum, off);
    if (lane == 0) out[gw] = sum + b4[0];
}

// ---------------------------------------------------------------------------
extern "C" void kernel_launch(void* const* d_in, const int* in_sizes, int n_in,
                              void* d_out, int out_size)
{
    (void)in_sizes; (void)n_in; (void)out_size;
    const float* x  = (const float*)d_in[0];
    const float* W1 = (const float*)d_in[1];
    const float* b1 = (const float*)d_in[2];
    const float* W2 = (const float*)d_in[3];
    const float* b2 = (const float*)d_in[4];
    const float* T  = (const float*)d_in[5];
    const float* W3 = (const float*)d_in[6];
    const float* b3 = (const float*)d_in[7];
    const float* W4 = (const float*)d_in[8];
    const float* b4 = (const float*)d_in[9];
    float* out = (float*)d_out;

    float *p1, *p2, *p3, *p4;
    __nv_bfloat16 *Wbh, *Wbl, *xbh, *xbl, *h1bh, *h1bl, *zbh, *zbl;
    cudaGetSymbolAddress((void**)&p1, g_p1);
    cudaGetSymbolAddress((void**)&p2, g_p2);
    cudaGetSymbolAddress((void**)&p3, g_p3);
    cudaGetSymbolAddress((void**)&p4, g_p4);
    cudaGetSymbolAddress((void**)&Wbh, g_Wbh);
    cudaGetSymbolAddress((void**)&Wbl, g_Wbl);
    cudaGetSymbolAddress((void**)&xbh, g_xbh);
    cudaGetSymbolAddress((void**)&xbl, g_xbl);
    cudaGetSymbolAddress((void**)&h1bh, g_h1bh);
    cudaGetSymbolAddress((void**)&h1bl, g_h1bl);
    cudaGetSymbolAddress((void**)&zbh, g_zbh);
    cudaGetSymbolAddress((void**)&zbl, g_zbl);

    // Prep: weights (848 blocks) + x conversion (512 blocks)
    prep_k<<<1360, 256>>>(W1, W2, T, W3, x);

    // GEMM1: x @ W1 (split-K=4, Kc=256), 256 CTAs
    tgemm<<<dim3(8,8,4), 128>>>(xbh, xbl, FDIM, Wbh + WOFF_W1, Wbl + WOFF_W1, FDIM,
                                p1, (size_t)BDIM * H1D, H1D, 256);
    // h1 = lrelu(sum4 + b1) -> bf16 hi/lo
    reduce_k<4><<<256, 256>>>(p1, (size_t)BDIM * H1D, H1D, b1,
                              h1bh, h1bl, H1D, 65536);

    // GEMM2: h1 @ W2 (split-K=4, Kc=128), 128 CTAs
    tgemm<<<dim3(4,8,4), 128>>>(h1bh, h1bl, H1D, Wbh + WOFF_W2, Wbl + WOFF_W2, H1D,
                                p2, (size_t)BDIM * H2D, H2D, 128);
    // z[:, :256] = lrelu(sum4 + b2) -> bf16 hi/lo (ld 384)
    reduce_k<4><<<128, 256>>>(p2, (size_t)BDIM * H2D, H2D, b2,
                              zbh, zbl, ZD, 32768);

    // GEMM3: h2 @ T (split-K=2, Kc=128), 160 CTAs (raw partials -> pairwise)
    tgemm<<<dim3(10,8,2), 128>>>(zbh, zbl, ZD, Wbh + WOFF_T, Wbl + WOFF_T, H2D,
                                 p3, (size_t)BDIM * NMD, NMD, 128);

    // Pairwise (fused p3 reduce + log2e) -> z cols 256..383 (bf16 hi/lo)
    pairwise_k<<<dim3(OUTD, 2), 256>>>(p3, zbh, zbl);

    // GEMM4: z @ W3 (split-K=3, Kc=128), 48 CTAs (raw partials -> final)
    tgemm<<<dim3(2,8,3), 128>>>(zbh, zbl, ZD, Wbh + WOFF_W3, Wbl + WOFF_W3, ZD,
                                p4, (size_t)BDIM * OUTD, OUTD, 128);

    // Final (fused p4 reduce + b3 + lrelu) -> out
    final_k<<<64, 256>>>(p4, b3, W4, b4, out);
}

// round 16
// speedup vs baseline: 1.0252x; 1.0252x over previous
#include <cuda_runtime.h>
#include <cuda_bf16.h>
#include <cstdint>

#define BDIM 512
#define FDIM 1024
#define H1D  512
#define H2D  256
#define OUTD 128
#define KDD  5
#define NMD  (OUTD*KDD)   // 640
#define ZD   384
#define LOG2E 1.44269504f

// Prepped weights: bf16 hi/lo, transposed to [n][k]
#define WOFF_W1 0
#define WOFF_W2 524288
#define WOFF_T  655360
#define WOFF_W3 819200
#define WTOT    868352
__device__ __nv_bfloat16 g_Wbh[WTOT];
__device__ __nv_bfloat16 g_Wbl[WTOT];

// bf16 hi/lo activations
__device__ __nv_bfloat16 g_xbh[BDIM * FDIM], g_xbl[BDIM * FDIM];
__device__ __nv_bfloat16 g_h1bh[BDIM * H1D], g_h1bl[BDIM * H1D];
__device__ __nv_bfloat16 g_zbh[BDIM * ZD],  g_zbl[BDIM * ZD];   // h2 | o_b

// fp32 split-K partials
__device__ float g_p1[4 * BDIM * H1D];
__device__ float g_p2[4 * BDIM * H2D];
__device__ float g_p3[2 * BDIM * NMD];
__device__ float g_p4[3 * BDIM * OUTD];

__device__ __forceinline__ float lrelu(float v) { return fmaxf(v, 0.2f * v); }

__device__ __forceinline__ uint32_t smem_u32(const void* p) {
    uint32_t a;
    asm("{ .reg .u64 t; cvta.to.shared.u64 t, %1; cvt.u32.u64 %0, t; }"
        : "=r"(a) : "l"(p));
    return a;
}
__device__ __forceinline__ void ldmx4(uint32_t* r, uint32_t addr) {
    asm volatile("ldmatrix.sync.aligned.m8n8.x4.shared.b16 {%0,%1,%2,%3}, [%4];"
                 : "=r"(r[0]), "=r"(r[1]), "=r"(r[2]), "=r"(r[3]) : "r"(addr));
}
__device__ __forceinline__ void mma16816(float* d, const uint32_t* a,
                                         uint32_t b0, uint32_t b1) {
    asm volatile("mma.sync.aligned.m16n8k16.row.col.f32.bf16.bf16.f32 "
                 "{%0,%1,%2,%3}, {%4,%5,%6,%7}, {%8,%9}, {%0,%1,%2,%3};"
                 : "+f"(d[0]), "+f"(d[1]), "+f"(d[2]), "+f"(d[3])
                 : "r"(a[0]), "r"(a[1]), "r"(a[2]), "r"(a[3]), "r"(b0), "r"(b1));
}
__device__ __forceinline__ uint32_t bf16pack(float lo_elem, float hi_elem) {
    uint32_t r;
    asm("cvt.rn.bf16x2.f32 %0, %1, %2;" : "=r"(r) : "f"(hi_elem), "f"(lo_elem));
    return r;
}
__device__ __forceinline__ void cpasync16(uint32_t dst, const void* src) {
    asm volatile("cp.async.cg.shared.global [%0], [%1], 16;"
                 :: "r"(dst), "l"(src) : "memory");
}
#define CP_COMMIT() asm volatile("cp.async.commit_group;" ::: "memory")
#define CP_WAIT1()  asm volatile("cp.async.wait_group 1;" ::: "memory")

// ---------------------------------------------------------------------------
// Prep: weights W [K][N] -> [n][k] bf16 hi/lo (blocks 0..847)
//       x [m][k] fp32 -> bf16 hi/lo straight convert (blocks 848..1359)
// ---------------------------------------------------------------------------
__global__ __launch_bounds__(256)
void prep_k(const float* __restrict__ W1, const float* __restrict__ W2,
            const float* __restrict__ T,  const float* __restrict__ W3,
            const float* __restrict__ x)
{
    int b = blockIdx.x;
    if (b >= 848) {
        int base = (b - 848) * 1024 + threadIdx.x * 4;
        float4 v = *(const float4*)(x + base);
        __nv_bfloat16 hx = __float2bfloat16_rn(v.x);
        __nv_bfloat16 hy = __float2bfloat16_rn(v.y);
        __nv_bfloat16 hz = __float2bfloat16_rn(v.z);
        __nv_bfloat16 hw = __float2bfloat16_rn(v.w);
        uint2 hp = make_uint2(bf16pack(v.x, v.y), bf16pack(v.z, v.w));
        uint2 lp = make_uint2(
            bf16pack(v.x - __bfloat162float(hx), v.y - __bfloat162float(hy)),
            bf16pack(v.z - __bfloat162float(hz), v.w - __bfloat162float(hw)));
        *(uint2*)(g_xbh + base) = hp;
        *(uint2*)(g_xbl + base) = lp;
        return;
    }
    __shared__ float s[32][33];
    const float* src; int K, N; size_t off; int rel;
    if      (b < 512) { src = W1; K = 1024; N = 512; off = WOFF_W1; rel = b; }
    else if (b < 640) { src = W2; K = 512;  N = 256; off = WOFF_W2; rel = b - 512; }
    else if (b < 800) { src = T;  K = 256;  N = 640; off = WOFF_T;  rel = b - 640; }
    else              { src = W3; K = 384;  N = 128; off = WOFF_W3; rel = b - 800; }
    int ktiles = K / 32;
    int k0 = (rel % ktiles) * 32, n0 = (rel / ktiles) * 32;
    int tx = threadIdx.x & 31, ty = threadIdx.x >> 5;

    #pragma unroll
    for (int i = 0; i < 4; i++)
        s[ty + i * 8][tx] = src[(size_t)(k0 + ty + i * 8) * N + n0 + tx];
    __syncthreads();
    #pragma unroll
    for (int i = 0; i < 4; i++) {
        int n = n0 + ty + i * 8, k = k0 + tx;
        float v = s[tx][ty + i * 8];
        __nv_bfloat16 h = __float2bfloat16_rn(v);
        float l = v - __bfloat162float(h);
        g_Wbh[off + (size_t)n * K + k] = h;
        g_Wbl[off + (size_t)n * K + k] = __float2bfloat16_rn(l);
    }
}

// ---------------------------------------------------------------------------
// Pure-bf16 tensor GEMM, cp.async 2-stage pipeline (round-14 proven, verbatim).
// CTA 64x64, 128 threads, K-chunks of 32, raw fp32 partial per split.
// ---------------------------------------------------------------------------
#define SA_ST 80
#define STG_A_H 0
#define STG_A_L 5120
#define STG_B_H 10240
#define STG_B_L 15360
#define STG_SZ  20480

__global__ __launch_bounds__(128)
void tgemm(const __nv_bfloat16* __restrict__ Abh,
           const __nv_bfloat16* __restrict__ Abl, int lda,
           const __nv_bfloat16* __restrict__ Bhg,
           const __nv_bfloat16* __restrict__ Blg, int Kb,
           float* __restrict__ Cpart, size_t cpStride, int ldc, int Kc)
{
    __shared__ __align__(16) char sb[2 * STG_SZ];
    const int tid = threadIdx.x, lane = tid & 31, wid = tid >> 5;
    const int wm = wid >> 1, wn = wid & 1;
    const int n0 = blockIdx.x * 64, row0 = blockIdx.y * 64;
    const int kbase = blockIdx.z * Kc;
    const uint32_t sbase = smem_u32(sb);

    float acc[2][4][4] = {};

    const int q0 = tid * 2;
    const int r0q = q0 >> 2, qi0 = q0 & 3;
    const int r1q = (q0 + 1) >> 2, qi1 = (q0 + 1) & 3;

    auto issue = [&](int k0, int stg) {
        uint32_t base = sbase + stg * STG_SZ;
        cpasync16(base + STG_A_H + r0q * SA_ST + qi0 * 16,
                  Abh + (size_t)(row0 + r0q) * lda + k0 + qi0 * 8);
        cpasync16(base + STG_A_H + r1q * SA_ST + qi1 * 16,
                  Abh + (size_t)(row0 + r1q) * lda + k0 + qi1 * 8);
        cpasync16(base + STG_A_L + r0q * SA_ST + qi0 * 16,
                  Abl + (size_t)(row0 + r0q) * lda + k0 + qi0 * 8);
        cpasync16(base + STG_A_L + r1q * SA_ST + qi1 * 16,
                  Abl + (size_t)(row0 + r1q) * lda + k0 + qi1 * 8);
        cpasync16(base + STG_B_H + r0q * SA_ST + qi0 * 16,
                  Bhg + (size_t)(n0 + r0q) * Kb + k0 + qi0 * 8);
        cpasync16(base + STG_B_H + r1q * SA_ST + qi1 * 16,
                  Bhg + (size_t)(n0 + r1q) * Kb + k0 + qi1 * 8);
        cpasync16(base + STG_B_L + r0q * SA_ST + qi0 * 16,
                  Blg + (size_t)(n0 + r0q) * Kb + k0 + qi0 * 8);
        cpasync16(base + STG_B_L + r1q * SA_ST + qi1 * 16,
                  Blg + (size_t)(n0 + r1q) * Kb + k0 + qi1 * 8);
    };

    const int nch = Kc / 32;
    issue(kbase, 0);          CP_COMMIT();
    issue(kbase + 32, 1);     CP_COMMIT();

    for (int ch = 0; ch < nch; ch++) {
        CP_WAIT1();
        __syncthreads();

        const uint32_t stg = sbase + (ch & 1) * STG_SZ;
        #pragma unroll
        for (int kt = 0; kt < 2; kt++) {
            uint32_t afh[2][4], afl[2][4], bfh[2][4], bfl[2][4];
            #pragma unroll
            for (int mt = 0; mt < 2; mt++) {
                uint32_t ad = stg + STG_A_H + (wm * 32 + mt * 16 + (lane & 15)) * SA_ST
                            + kt * 32 + ((lane >> 4) << 4);
                ldmx4(afh[mt], ad);
                ldmx4(afl[mt], ad + (STG_A_L - STG_A_H));
            }
            #pragma unroll
            for (int bt = 0; bt < 2; bt++) {
                uint32_t bd = stg + STG_B_H + (wn * 32 + bt * 16 + (lane & 15)) * SA_ST
                            + kt * 32 + ((lane >> 4) << 4);
                ldmx4(bfh[bt], bd);
                ldmx4(bfl[bt], bd + (STG_B_L - STG_B_H));
            }
            #pragma unroll
            for (int mt = 0; mt < 2; mt++)
                #pragma unroll
                for (int j = 0; j < 4; j++) {
                    int t = j >> 1, o = j & 1;
                    uint32_t b0h = bfh[t][o], b1h = bfh[t][o + 2];
                    uint32_t b0l = bfl[t][o], b1l = bfl[t][o + 2];
                    mma16816(acc[mt][j], afh[mt], b0h, b1h);
                    mma16816(acc[mt][j], afl[mt], b0h, b1h);
                    mma16816(acc[mt][j], afh[mt], b0l, b1l);
                }
        }
        __syncthreads();
        if (ch + 2 < nch) issue(kbase + (ch + 2) * 32, ch & 1);
        CP_COMMIT();
    }

    float* cp = Cpart + (size_t)blockIdx.z * cpStride;
    #pragma unroll
    for (int mt = 0; mt < 2; mt++)
        #pragma unroll
        for (int j = 0; j < 4; j++) {
            int r = row0 + wm * 32 + mt * 16 + (lane >> 2);
            int c = n0 + wn * 32 + j * 8 + (lane & 3) * 2;
            *(float2*)&cp[(size_t)r * ldc + c] =
                make_float2(acc[mt][j][0], acc[mt][j][1]);
            *(float2*)&cp[(size_t)(r + 8) * ldc + c] =
                make_float2(acc[mt][j][2], acc[mt][j][3]);
        }
}

// ---------------------------------------------------------------------------
// Reduce SPLIT partials -> lrelu(v+bias) -> bf16 hi/lo (for GEMM1/GEMM2 out).
// ---------------------------------------------------------------------------
template<int SPLIT>
__global__ __launch_bounds__(256)
void reduce_k(const float* __restrict__ P, size_t pstride, int ncols,
              const float* __restrict__ bias,
              __nv_bfloat16* __restrict__ OutH, __nv_bfloat16* __restrict__ OutL,
              int ld_out, int total4)
{
    int f = blockIdx.x * 256 + threadIdx.x;
    if (f >= total4) return;
    int e = f * 4;
    int row = e / ncols, c = e - row * ncols;
    const float* p = P + (size_t)row * ncols + c;
    float4 v = *(const float4*)p;
    #pragma unroll
    for (int s = 1; s < SPLIT; s++) {
        float4 u = *(const float4*)(p + (size_t)s * pstride);
        v.x += u.x; v.y += u.y; v.z += u.z; v.w += u.w;
    }
    float4 bv = *(const float4*)(bias + c);
    v.x = lrelu(v.x + bv.x);
    v.y = lrelu(v.y + bv.y);
    v.z = lrelu(v.z + bv.z);
    v.w = lrelu(v.w + bv.w);
    __nv_bfloat16 hx = __float2bfloat16_rn(v.x);
    __nv_bfloat16 hy = __float2bfloat16_rn(v.y);
    __nv_bfloat16 hz = __float2bfloat16_rn(v.z);
    __nv_bfloat16 hw = __float2bfloat16_rn(v.w);
    uint2 hp = make_uint2(bf16pack(v.x, v.y), bf16pack(v.z, v.w));
    uint2 lp = make_uint2(
        bf16pack(v.x - __bfloat162float(hx), v.y - __bfloat162float(hy)),
        bf16pack(v.z - __bfloat162float(hz), v.w - __bfloat162float(hw)));
    *(uint2*)(OutH + (size_t)row * ld_out + c) = hp;
    *(uint2*)(OutL + (size_t)row * ld_out + c) = lp;
}

// ---------------------------------------------------------------------------
// Pairwise with fused GEMM3 split-K reduction (scalar inner loop, round-14
// proven form): loads both p3 partials, sums, scales by log2e into smem;
// o_b[j,o] = sum_i exp2(-|M[i,o,:]-M[j,o,:]|_1) - 1.
// grid (o=128, jh=2), 256 threads. Writes bf16 hi/lo into z cols 256+o.
// ---------------------------------------------------------------------------
__global__ __launch_bounds__(256)
void pairwise_k(const float* __restrict__ P3,
                __nv_bfloat16* __restrict__ zbh, __nv_bfloat16* __restrict__ zbl)
{
    __shared__ float4 s4[BDIM];
    __shared__ float  s1[BDIM];
    const int o = blockIdx.x, jh = blockIdx.y;
    const int tid = threadIdx.x;
    const size_t MS = (size_t)BDIM * NMD;

    #pragma unroll
    for (int it = 0; it < 10; it++) {
        int idx = tid + it * 256;
        int i = idx / 5, k = idx - i * 5;
        const float* p = P3 + (size_t)i * NMD + o * KDD + k;
        float v = (p[0] + p[MS]) * LOG2E;
        if (k < 4) ((float*)s4)[i * 4 + k] = v;
        else       s1[i] = v;
    }
    __syncthreads();

    const int j = jh * 256 + tid;
    float4 m4 = s4[j];
    float  m4e = s1[j];

    float acc0 = 0.f, acc1 = 0.f;
    #pragma unroll 8
    for (int i = 0; i < BDIM; i++) {
        float4 v = s4[i];
        float  w = s1[i];
        float n = fabsf(v.x - m4.x) + fabsf(v.y - m4.y) + fabsf(v.z - m4.z)
                + fabsf(v.w - m4.w) + fabsf(w - m4e);
        float e;
        asm("ex2.approx.f32 %0, %1;" : "=f"(e) : "f"(-n));
        if (i & 1) acc1 += e; else acc0 += e;
    }
    float val = acc0 + acc1 - 1.0f;
    __nv_bfloat16 h = __float2bfloat16_rn(val);
    zbh[(size_t)j * ZD + H2D + o] = h;
    zbl[(size_t)j * ZD + H2D + o] = __float2bfloat16_rn(val - __bfloat162float(h));
}

// ---------------------------------------------------------------------------
// Final with fused GEMM4 split-K reduction:
// z3 = lrelu(sum3 p4 + b3); out = z3 @ W4 + b4. One warp per batch row.
// ---------------------------------------------------------------------------
__global__ __launch_bounds__(256)
void final_k(const float* __restrict__ p4, const float* __restrict__ b3,
             const float* __restrict__ W4, const float* __restrict__ b4,
             float* __restrict__ out)
{
    const size_t ZS = (size_t)BDIM * OUTD;
    int gw = blockIdx.x * 8 + (threadIdx.x >> 5);
    int lane = threadIdx.x & 31;
    float sum = 0.f;
    #pragma unroll
    for (int it = 0; it < 4; it++) {
        int k = it * 32 + lane;
        const float* p = p4 + (size_t)gw * OUTD + k;
        float v = (p[0] + p[ZS]) + p[2 * ZS] + b3[k];
        v = lrelu(v);
        sum += v * W4[k];
    }
    #pragma unroll
    for (int off = 16; off; off >>= 1)
        sum += __shfl_xor_sync(0xffffffffu, sum, off);
    if (lane == 0) out[gw] = sum + b4[0];
}

// ---------------------------------------------------------------------------
extern "C" void kernel_launch(void* const* d_in, const int* in_sizes, int n_in,
                              void* d_out, int out_size)
{
    (void)in_sizes; (void)n_in; (void)out_size;
    const float* x  = (const float*)d_in[0];
    const float* W1 = (const float*)d_in[1];
    const float* b1 = (const float*)d_in[2];
    const float* W2 = (const float*)d_in[3];
    const float* b2 = (const float*)d_in[4];
    const float* T  = (const float*)d_in[5];
    const float* W3 = (const float*)d_in[6];
    const float* b3 = (const float*)d_in[7];
    const float* W4 = (const float*)d_in[8];
    const float* b4 = (const float*)d_in[9];
    float* out = (float*)d_out;

    float *p1, *p2, *p3, *p4;
    __nv_bfloat16 *Wbh, *Wbl, *xbh, *xbl, *h1bh, *h1bl, *zbh, *zbl;
    cudaGetSymbolAddress((void**)&p1, g_p1);
    cudaGetSymbolAddress((void**)&p2, g_p2);
    cudaGetSymbolAddress((void**)&p3, g_p3);
    cudaGetSymbolAddress((void**)&p4, g_p4);
    cudaGetSymbolAddress((void**)&Wbh, g_Wbh);
    cudaGetSymbolAddress((void**)&Wbl, g_Wbl);
    cudaGetSymbolAddress((void**)&xbh, g_xbh);
    cudaGetSymbolAddress((void**)&xbl, g_xbl);
    cudaGetSymbolAddress((void**)&h1bh, g_h1bh);
    cudaGetSymbolAddress((void**)&h1bl, g_h1bl);
    cudaGetSymbolAddress((void**)&zbh, g_zbh);
    cudaGetSymbolAddress((void**)&zbl, g_zbl);

    // Prep: weights (848 blocks) + x conversion (512 blocks)
    prep_k<<<1360, 256>>>(W1, W2, T, W3, x);

    // GEMM1: x @ W1 (split-K=4, Kc=256), 256 CTAs
    tgemm<<<dim3(8,8,4), 128>>>(xbh, xbl, FDIM, Wbh + WOFF_W1, Wbl + WOFF_W1, FDIM,
                                p1, (size_t)BDIM * H1D, H1D, 256);
    // h1 = lrelu(sum4 + b1) -> bf16 hi/lo
    reduce_k<4><<<256, 256>>>(p1, (size_t)BDIM * H1D, H1D, b1,
                              h1bh, h1bl, H1D, 65536);

    // GEMM2: h1 @ W2 (split-K=4, Kc=128), 128 CTAs
    tgemm<<<dim3(4,8,4), 128>>>(h1bh, h1bl, H1D, Wbh + WOFF_W2, Wbl + WOFF_W2, H1D,
                                p2, (size_t)BDIM * H2D, H2D, 128);
    // z[:, :256] = lrelu(sum4 + b2) -> bf16 hi/lo (ld 384)
    reduce_k<4><<<128, 256>>>(p2, (size_t)BDIM * H2D, H2D, b2,
                              zbh, zbl, ZD, 32768);

    // GEMM3: h2 @ T (split-K=2, Kc=128), 160 CTAs (raw partials -> pairwise)
    tgemm<<<dim3(10,8,2), 128>>>(zbh, zbl, ZD, Wbh + WOFF_T, Wbl + WOFF_T, H2D,
                                 p3, (size_t)BDIM * NMD, NMD, 128);

    // Pairwise (fused p3 reduce + log2e) -> z cols 256..383 (bf16 hi/lo)
    pairwise_k<<<dim3(OUTD, 2), 256>>>(p3, zbh, zbl);

    // GEMM4: z @ W3 (split-K=3, Kc=128), 48 CTAs (raw partials -> final)
    tgemm<<<dim3(2,8,3), 128>>>(zbh, zbl, ZD, Wbh + WOFF_W3, Wbl + WOFF_W3, ZD,
                                p4, (size_t)BDIM * OUTD, OUTD, 128);

    // Final (fused p4 reduce + b3 + lrelu) -> out
    final_k<<<64, 256>>>(p4, b3, W4, b4, out);
}

// round 17
// speedup vs baseline: 1.5855x; 1.5465x over previous
#include <cuda_runtime.h>
#include <cuda_bf16.h>
#include <cstdint>

#define BDIM 512
#define FDIM 1024
#define H1D  512
#define H2D  256
#define OUTD 128
#define KDD  5
#define NMD  (OUTD*KDD)   // 640
#define ZD   384
#define LOG2E 1.44269504f

// Prepped weights: bf16 hi/lo, transposed to [n][k]
#define WOFF_W1 0
#define WOFF_W2 524288
#define WOFF_T  655360
#define WOFF_W3 819200
#define WTOT    868352
__device__ __nv_bfloat16 g_Wbh[WTOT];
__device__ __nv_bfloat16 g_Wbl[WTOT];

// bf16 hi/lo activations
__device__ __nv_bfloat16 g_xbh[BDIM * FDIM], g_xbl[BDIM * FDIM];
__device__ __nv_bfloat16 g_h1bh[BDIM * H1D], g_h1bl[BDIM * H1D];
__device__ __nv_bfloat16 g_zbh[BDIM * ZD],  g_zbl[BDIM * ZD];   // h2 | o_b

// fp32 split-K partials
__device__ float g_p1[4 * BDIM * H1D];
__device__ float g_p2[8 * BDIM * H2D];
__device__ float g_p3[2 * BDIM * NMD];
__device__ float g_p4[6 * BDIM * OUTD];

__device__ __forceinline__ float lrelu(float v) { return fmaxf(v, 0.2f * v); }

__device__ __forceinline__ uint32_t smem_u32(const void* p) {
    uint32_t a;
    asm("{ .reg .u64 t; cvta.to.shared.u64 t, %1; cvt.u32.u64 %0, t; }"
        : "=r"(a) : "l"(p));
    return a;
}
__device__ __forceinline__ void ldmx4(uint32_t* r, uint32_t addr) {
    asm volatile("ldmatrix.sync.aligned.m8n8.x4.shared.b16 {%0,%1,%2,%3}, [%4];"
                 : "=r"(r[0]), "=r"(r[1]), "=r"(r[2]), "=r"(r[3]) : "r"(addr));
}
__device__ __forceinline__ void mma16816(float* d, const uint32_t* a,
                                         uint32_t b0, uint32_t b1) {
    asm volatile("mma.sync.aligned.m16n8k16.row.col.f32.bf16.bf16.f32 "
                 "{%0,%1,%2,%3}, {%4,%5,%6,%7}, {%8,%9}, {%0,%1,%2,%3};"
                 : "+f"(d[0]), "+f"(d[1]), "+f"(d[2]), "+f"(d[3])
                 : "r"(a[0]), "r"(a[1]), "r"(a[2]), "r"(a[3]), "r"(b0), "r"(b1));
}
__device__ __forceinline__ uint32_t bf16pack(float lo_elem, float hi_elem) {
    uint32_t r;
    asm("cvt.rn.bf16x2.f32 %0, %1, %2;" : "=r"(r) : "f"(hi_elem), "f"(lo_elem));
    return r;
}
__device__ __forceinline__ void cpasync16(uint32_t dst, const void* src) {
    asm volatile("cp.async.cg.shared.global [%0], [%1], 16;"
                 :: "r"(dst), "l"(src) : "memory");
}
#define CP_COMMIT() asm volatile("cp.async.commit_group;" ::: "memory")
#define CP_WAIT1()  asm volatile("cp.async.wait_group 1;" ::: "memory")

// ---------------------------------------------------------------------------
// Prep: weights W [K][N] -> [n][k] bf16 hi/lo (blocks 0..847)
//       x [m][k] fp32 -> bf16 hi/lo straight convert (blocks 848..1359)
// ---------------------------------------------------------------------------
__global__ __launch_bounds__(256)
void prep_k(const float* __restrict__ W1, const float* __restrict__ W2,
            const float* __restrict__ T,  const float* __restrict__ W3,
            const float* __restrict__ x)
{
    int b = blockIdx.x;
    if (b >= 848) {
        int base = (b - 848) * 1024 + threadIdx.x * 4;
        float4 v = *(const float4*)(x + base);
        __nv_bfloat16 hx = __float2bfloat16_rn(v.x);
        __nv_bfloat16 hy = __float2bfloat16_rn(v.y);
        __nv_bfloat16 hz = __float2bfloat16_rn(v.z);
        __nv_bfloat16 hw = __float2bfloat16_rn(v.w);
        uint2 hp = make_uint2(bf16pack(v.x, v.y), bf16pack(v.z, v.w));
        uint2 lp = make_uint2(
            bf16pack(v.x - __bfloat162float(hx), v.y - __bfloat162float(hy)),
            bf16pack(v.z - __bfloat162float(hz), v.w - __bfloat162float(hw)));
        *(uint2*)(g_xbh + base) = hp;
        *(uint2*)(g_xbl + base) = lp;
        return;
    }
    __shared__ float s[32][33];
    const float* src; int K, N; size_t off; int rel;
    if      (b < 512) { src = W1; K = 1024; N = 512; off = WOFF_W1; rel = b; }
    else if (b < 640) { src = W2; K = 512;  N = 256; off = WOFF_W2; rel = b - 512; }
    else if (b < 800) { src = T;  K = 256;  N = 640; off = WOFF_T;  rel = b - 640; }
    else              { src = W3; K = 384;  N = 128; off = WOFF_W3; rel = b - 800; }
    int ktiles = K / 32;
    int k0 = (rel % ktiles) * 32, n0 = (rel / ktiles) * 32;
    int tx = threadIdx.x & 31, ty = threadIdx.x >> 5;

    #pragma unroll
    for (int i = 0; i < 4; i++)
        s[ty + i * 8][tx] = src[(size_t)(k0 + ty + i * 8) * N + n0 + tx];
    __syncthreads();
    #pragma unroll
    for (int i = 0; i < 4; i++) {
        int n = n0 + ty + i * 8, k = k0 + tx;
        float v = s[tx][ty + i * 8];
        __nv_bfloat16 h = __float2bfloat16_rn(v);
        float l = v - __bfloat162float(h);
        g_Wbh[off + (size_t)n * K + k] = h;
        g_Wbl[off + (size_t)n * K + k] = __float2bfloat16_rn(l);
    }
}

// ---------------------------------------------------------------------------
// Pure-bf16 tensor GEMM, cp.async 2-stage pipeline (round-14 proven, verbatim).
// CTA 64x64, 128 threads, K-chunks of 32, raw fp32 partial per split.
// ---------------------------------------------------------------------------
#define SA_ST 80
#define STG_A_H 0
#define STG_A_L 5120
#define STG_B_H 10240
#define STG_B_L 15360
#define STG_SZ  20480

__global__ __launch_bounds__(128)
void tgemm(const __nv_bfloat16* __restrict__ Abh,
           const __nv_bfloat16* __restrict__ Abl, int lda,
           const __nv_bfloat16* __restrict__ Bhg,
           const __nv_bfloat16* __restrict__ Blg, int Kb,
           float* __restrict__ Cpart, size_t cpStride, int ldc, int Kc)
{
    __shared__ __align__(16) char sb[2 * STG_SZ];
    const int tid = threadIdx.x, lane = tid & 31, wid = tid >> 5;
    const int wm = wid >> 1, wn = wid & 1;
    const int n0 = blockIdx.x * 64, row0 = blockIdx.y * 64;
    const int kbase = blockIdx.z * Kc;
    const uint32_t sbase = smem_u32(sb);

    float acc[2][4][4] = {};

    const int q0 = tid * 2;
    const int r0q = q0 >> 2, qi0 = q0 & 3;
    const int r1q = (q0 + 1) >> 2, qi1 = (q0 + 1) & 3;

    auto issue = [&](int k0, int stg) {
        uint32_t base = sbase + stg * STG_SZ;
        cpasync16(base + STG_A_H + r0q * SA_ST + qi0 * 16,
                  Abh + (size_t)(row0 + r0q) * lda + k0 + qi0 * 8);
        cpasync16(base + STG_A_H + r1q * SA_ST + qi1 * 16,
                  Abh + (size_t)(row0 + r1q) * lda + k0 + qi1 * 8);
        cpasync16(base + STG_A_L + r0q * SA_ST + qi0 * 16,
                  Abl + (size_t)(row0 + r0q) * lda + k0 + qi0 * 8);
        cpasync16(base + STG_A_L + r1q * SA_ST + qi1 * 16,
                  Abl + (size_t)(row0 + r1q) * lda + k0 + qi1 * 8);
        cpasync16(base + STG_B_H + r0q * SA_ST + qi0 * 16,
                  Bhg + (size_t)(n0 + r0q) * Kb + k0 + qi0 * 8);
        cpasync16(base + STG_B_H + r1q * SA_ST + qi1 * 16,
                  Bhg + (size_t)(n0 + r1q) * Kb + k0 + qi1 * 8);
        cpasync16(base + STG_B_L + r0q * SA_ST + qi0 * 16,
                  Blg + (size_t)(n0 + r0q) * Kb + k0 + qi0 * 8);
        cpasync16(base + STG_B_L + r1q * SA_ST + qi1 * 16,
                  Blg + (size_t)(n0 + r1q) * Kb + k0 + qi1 * 8);
    };

    const int nch = Kc / 32;
    issue(kbase, 0);          CP_COMMIT();
    issue(kbase + 32, 1);     CP_COMMIT();

    for (int ch = 0; ch < nch; ch++) {
        CP_WAIT1();
        __syncthreads();

        const uint32_t stg = sbase + (ch & 1) * STG_SZ;
        #pragma unroll
        for (int kt = 0; kt < 2; kt++) {
            uint32_t afh[2][4], afl[2][4], bfh[2][4], bfl[2][4];
            #pragma unroll
            for (int mt = 0; mt < 2; mt++) {
                uint32_t ad = stg + STG_A_H + (wm * 32 + mt * 16 + (lane & 15)) * SA_ST
                            + kt * 32 + ((lane >> 4) << 4);
                ldmx4(afh[mt], ad);
                ldmx4(afl[mt], ad + (STG_A_L - STG_A_H));
            }
            #pragma unroll
            for (int bt = 0; bt < 2; bt++) {
                uint32_t bd = stg + STG_B_H + (wn * 32 + bt * 16 + (lane & 15)) * SA_ST
                            + kt * 32 + ((lane >> 4) << 4);
                ldmx4(bfh[bt], bd);
                ldmx4(bfl[bt], bd + (STG_B_L - STG_B_H));
            }
            #pragma unroll
            for (int mt = 0; mt < 2; mt++)
                #pragma unroll
                for (int j = 0; j < 4; j++) {
                    int t = j >> 1, o = j & 1;
                    uint32_t b0h = bfh[t][o], b1h = bfh[t][o + 2];
                    uint32_t b0l = bfl[t][o], b1l = bfl[t][o + 2];
                    mma16816(acc[mt][j], afh[mt], b0h, b1h);
                    mma16816(acc[mt][j], afl[mt], b0h, b1h);
                    mma16816(acc[mt][j], afh[mt], b0l, b1l);
                }
        }
        __syncthreads();
        if (ch + 2 < nch) issue(kbase + (ch + 2) * 32, ch & 1);
        CP_COMMIT();
    }

    float* cp = Cpart + (size_t)blockIdx.z * cpStride;
    #pragma unroll
    for (int mt = 0; mt < 2; mt++)
        #pragma unroll
        for (int j = 0; j < 4; j++) {
            int r = row0 + wm * 32 + mt * 16 + (lane >> 2);
            int c = n0 + wn * 32 + j * 8 + (lane & 3) * 2;
            *(float2*)&cp[(size_t)r * ldc + c] =
                make_float2(acc[mt][j][0], acc[mt][j][1]);
            *(float2*)&cp[(size_t)(r + 8) * ldc + c] =
                make_float2(acc[mt][j][2], acc[mt][j][3]);
        }
}

// ---------------------------------------------------------------------------
// Reduce SPLIT partials -> lrelu(v+bias) -> bf16 hi/lo (for GEMM1/GEMM2 out).
// ---------------------------------------------------------------------------
template<int SPLIT>
__global__ __launch_bounds__(256)
void reduce_k(const float* __restrict__ P, size_t pstride, int ncols,
              const float* __restrict__ bias,
              __nv_bfloat16* __restrict__ OutH, __nv_bfloat16* __restrict__ OutL,
              int ld_out, int total4)
{
    int f = blockIdx.x * 256 + threadIdx.x;
    if (f >= total4) return;
    int e = f * 4;
    int row = e / ncols, c = e - row * ncols;
    const float* p = P + (size_t)row * ncols + c;
    float4 v = *(const float4*)p;
    #pragma unroll
    for (int s = 1; s < SPLIT; s++) {
        float4 u = *(const float4*)(p + (size_t)s * pstride);
        v.x += u.x; v.y += u.y; v.z += u.z; v.w += u.w;
    }
    float4 bv = *(const float4*)(bias + c);
    v.x = lrelu(v.x + bv.x);
    v.y = lrelu(v.y + bv.y);
    v.z = lrelu(v.z + bv.z);
    v.w = lrelu(v.w + bv.w);
    __nv_bfloat16 hx = __float2bfloat16_rn(v.x);
    __nv_bfloat16 hy = __float2bfloat16_rn(v.y);
    __nv_bfloat16 hz = __float2bfloat16_rn(v.z);
    __nv_bfloat16 hw = __float2bfloat16_rn(v.w);
    uint2 hp = make_uint2(bf16pack(v.x, v.y), bf16pack(v.z, v.w));
    uint2 lp = make_uint2(
        bf16pack(v.x - __bfloat162float(hx), v.y - __bfloat162float(hy)),
        bf16pack(v.z - __bfloat162float(hz), v.w - __bfloat162float(hw)));
    *(uint2*)(OutH + (size_t)row * ld_out + c) = hp;
    *(uint2*)(OutL + (size_t)row * ld_out + c) = lp;
}

// ---------------------------------------------------------------------------
// Pairwise with fused GEMM3 split-K reduction (scalar inner loop):
// o_b[j,o] = sum_i exp2(-|M[i,o,:]-M[j,o,:]|_1) - 1, M = (p3a+p3b)*log2e.
// grid (o=128, jh=2), 256 threads. Writes bf16 hi/lo into z cols 256+o.
// ---------------------------------------------------------------------------
__global__ __launch_bounds__(256)
void pairwise_k(const float* __restrict__ P3,
                __nv_bfloat16* __restrict__ zbh, __nv_bfloat16* __restrict__ zbl)
{
    __shared__ float4 s4[BDIM];
    __shared__ float  s1[BDIM];
    const int o = blockIdx.x, jh = blockIdx.y;
    const int tid = threadIdx.x;
    const size_t MS = (size_t)BDIM * NMD;

    #pragma unroll
    for (int it = 0; it < 10; it++) {
        int idx = tid + it * 256;
        int i = idx / 5, k = idx - i * 5;
        const float* p = P3 + (size_t)i * NMD + o * KDD + k;
        float v = (p[0] + p[MS]) * LOG2E;
        if (k < 4) ((float*)s4)[i * 4 + k] = v;
        else       s1[i] = v;
    }
    __syncthreads();

    const int j = jh * 256 + tid;
    float4 m4 = s4[j];
    float  m4e = s1[j];

    float acc0 = 0.f, acc1 = 0.f;
    #pragma unroll 8
    for (int i = 0; i < BDIM; i++) {
        float4 v = s4[i];
        float  w = s1[i];
        float n = fabsf(v.x - m4.x) + fabsf(v.y - m4.y) + fabsf(v.z - m4.z)
                + fabsf(v.w - m4.w) + fabsf(w - m4e);
        float e;
        asm("ex2.approx.f32 %0, %1;" : "=f"(e) : "f"(-n));
        if (i & 1) acc1 += e; else acc0 += e;
    }
    float val = acc0 + acc1 - 1.0f;
    __nv_bfloat16 h = __float2bfloat16_rn(val);
    zbh[(size_t)j * ZD + H2D + o] = h;
    zbl[(size_t)j * ZD + H2D + o] = __float2bfloat16_rn(val - __bfloat162float(h));
}

// ---------------------------------------------------------------------------
// Final with fused GEMM4 split-K reduction (6 partials):
// z3 = lrelu(sum6 p4 + b3); out = z3 @ W4 + b4. One warp per batch row.
// ---------------------------------------------------------------------------
__global__ __launch_bounds__(256)
void final_k(const float* __restrict__ p4, const float* __restrict__ b3,
             const float* __restrict__ W4, const float* __restrict__ b4,
             float* __restrict__ out)
{
    const size_t ZS = (size_t)BDIM * OUTD;
    int gw = blockIdx.x * 8 + (threadIdx.x >> 5);
    int lane = threadIdx.x & 31;
    float sum = 0.f;
    #pragma unroll
    for (int it = 0; it < 4; it++) {
        int k = it * 32 + lane;
        const float* p = p4 + (size_t)gw * OUTD + k;
        float v = ((p[0] + p[ZS]) + (p[2 * ZS] + p[3 * ZS]))
                + (p[4 * ZS] + p[5 * ZS]) + b3[k];
        v = lrelu(v);
        sum += v * W4[k];
    }
    #pragma unroll
    for (int off = 16; off; off >>= 1)
        sum += __shfl_xor_sync(0xffffffffu, sum, off);
    if (lane == 0) out[gw] = sum + b4[0];
}

// ---------------------------------------------------------------------------
extern "C" void kernel_launch(void* const* d_in, const int* in_sizes, int n_in,
                              void* d_out, int out_size)
{
    (void)in_sizes; (void)n_in; (void)out_size;
    const float* x  = (const float*)d_in[0];
    const float* W1 = (const float*)d_in[1];
    const float* b1 = (const float*)d_in[2];
    const float* W2 = (const float*)d_in[3];
    const float* b2 = (const float*)d_in[4];
    const float* T  = (const float*)d_in[5];
    const float* W3 = (const float*)d_in[6];
    const float* b3 = (const float*)d_in[7];
    const float* W4 = (const float*)d_in[8];
    const float* b4 = (const float*)d_in[9];
    float* out = (float*)d_out;

    float *p1, *p2, *p3, *p4;
    __nv_bfloat16 *Wbh, *Wbl, *xbh, *xbl, *h1bh, *h1bl, *zbh, *zbl;
    cudaGetSymbolAddress((void**)&p1, g_p1);
    cudaGetSymbolAddress((void**)&p2, g_p2);
    cudaGetSymbolAddress((void**)&p3, g_p3);
    cudaGetSymbolAddress((void**)&p4, g_p4);
    cudaGetSymbolAddress((void**)&Wbh, g_Wbh);
    cudaGetSymbolAddress((void**)&Wbl, g_Wbl);
    cudaGetSymbolAddress((void**)&xbh, g_xbh);
    cudaGetSymbolAddress((void**)&xbl, g_xbl);
    cudaGetSymbolAddress((void**)&h1bh, g_h1bh);
    cudaGetSymbolAddress((void**)&h1bl, g_h1bl);
    cudaGetSymbolAddress((void**)&zbh, g_zbh);
    cudaGetSymbolAddress((void**)&zbl, g_zbl);

    // Prep: weights (848 blocks) + x conversion (512 blocks)
    prep_k<<<1360, 256>>>(W1, W2, T, W3, x);

    // GEMM1: x @ W1 (split-K=4, Kc=256), 256 CTAs
    tgemm<<<dim3(8,8,4), 128>>>(xbh, xbl, FDIM, Wbh + WOFF_W1, Wbl + WOFF_W1, FDIM,
                                p1, (size_t)BDIM * H1D, H1D, 256);
    // h1 = lrelu(sum4 + b1) -> bf16 hi/lo
    reduce_k<4><<<256, 256>>>(p1, (size_t)BDIM * H1D, H1D, b1,
                              h1bh, h1bl, H1D, 65536);

    // GEMM2: h1 @ W2 (split-K=8, Kc=64), 4x8x8 = 256 CTAs
    tgemm<<<dim3(4,8,8), 128>>>(h1bh, h1bl, H1D, Wbh + WOFF_W2, Wbl + WOFF_W2, H1D,
                                p2, (size_t)BDIM * H2D, H2D, 64);
    // z[:, :256] = lrelu(sum8 + b2) -> bf16 hi/lo (ld 384)
    reduce_k<8><<<128, 256>>>(p2, (size_t)BDIM * H2D, H2D, b2,
                              zbh, zbl, ZD, 32768);

    // GEMM3: h2 @ T (split-K=2, Kc=128), 160 CTAs (raw partials -> pairwise)
    tgemm<<<dim3(10,8,2), 128>>>(zbh, zbl, ZD, Wbh + WOFF_T, Wbl + WOFF_T, H2D,
                                 p3, (size_t)BDIM * NMD, NMD, 128);

    // Pairwise (fused p3 reduce + log2e) -> z cols 256..383 (bf16 hi/lo)
    pairwise_k<<<dim3(OUTD, 2), 256>>>(p3, zbh, zbl);

    // GEMM4: z @ W3 (split-K=6, Kc=64), 2x8x6 = 96 CTAs (raw partials -> final)
    tgemm<<<dim3(2,8,6), 128>>>(zbh, zbl, ZD, Wbh + WOFF_W3, Wbl + WOFF_W3, ZD,
                                p4, (size_t)BDIM * OUTD, OUTD, 64);

    // Final (fused p4 reduce + b3 + lrelu) -> out
    final_k<<<64, 256>>>(p4, b3, W4, b4, out);
}